// round 15
// baseline (speedup 1.0000x reference)
#include <cuda_runtime.h>
#include <cuda_fp16.h>
#include <float.h>
#include <stdint.h>

// ---------------- problem constants ----------------
constexpr int N_ROWS  = 6272;
constexpr int M_BANK  = 32768;
constexpr int DIM     = 384;
constexpr int B_SZ    = 8;
constexpr int PATCHES = N_ROWS / B_SZ;
constexpr int KNN     = 9;

// ---------------- GEMM tiling (2 CTAs/SM, fp16 accum, A resident) ----------------
constexpr int BM = 64;
constexpr int BN = 256;
constexpr int BK = 64;                 // 128B per row chunk
constexpr int NCHUNK_K = DIM / BK;     // 6
constexpr int JT_TOTAL = M_BANK / BN;  // 128
constexpr int GRID_Y   = 3;
constexpr int ROW_TILES = N_ROWS / BM; // 98 -> 294 CTAs = one 2-deep wave
constexpr int NTHR = 256;              // 8 warps

constexpr int A_CHUNK_BYTES = BM * 128;                 // 8192
constexpr int OFF_B         = NCHUNK_K * A_CHUNK_BYTES; // 49152
constexpr int B_STAGE_BYTES = BN * 128;                 // 32768
constexpr int SMEM_BYTES    = OFF_B + 2 * B_STAGE_BYTES;// 114688 -> 2 CTAs/SM

// top-k staging
constexpr int SEGS = 32;
constexpr int SEG_LEN = M_BANK / SEGS;  // 1024

// ---------------- device scratch ----------------
__device__ __align__(256) __half g_Eh[N_ROWS * DIM];
__device__ __align__(256) __half g_Bh[M_BANK * DIM];
__device__ float              g_xnorm[N_ROWS];
__device__ float              g_ynorm[M_BANK];
__device__ unsigned long long g_packed[N_ROWS];
__device__ float              g_d2[B_SZ * M_BANK];
__device__ unsigned long long g_part[B_SZ * SEGS * KNN];
__device__ int                g_maxrow[B_SZ];
__device__ float              g_score[B_SZ];
__device__ int                g_nnidx[B_SZ];

// ---------------- helpers ----------------
__device__ __forceinline__ uint32_t smem_u32(const void* p) {
    uint32_t a;
    asm("{ .reg .u64 t; cvta.to.shared.u64 t, %1; cvt.u32.u64 %0, t; }"
        : "=r"(a) : "l"(p));
    return a;
}
__device__ __forceinline__ void cp16(uint32_t dst, const void* src) {
    asm volatile("cp.async.cg.shared.global [%0], [%1], 16;"
                 :: "r"(dst), "l"(src) : "memory");
}
#define CP_COMMIT() asm volatile("cp.async.commit_group;" ::: "memory")
#define CP_WAIT0()  asm volatile("cp.async.wait_group 0;" ::: "memory")

__device__ __forceinline__ uint32_t swz(uint32_t o) { return o ^ ((o >> 3) & 0x70); }

__device__ __forceinline__ void ldmA(uint32_t base, int r_base, int kb,
                                     int lane, uint32_t* f) {
    int q = lane >> 3;
    int r = r_base + (q & 1) * 8 + (lane & 7);
    int kk = kb + (q >> 1) * 16;
    uint32_t a = base + swz((uint32_t)(r * 128 + kk));
    asm volatile("ldmatrix.sync.aligned.m8n8.x4.shared.b16 {%0,%1,%2,%3}, [%4];"
                 : "=r"(f[0]), "=r"(f[1]), "=r"(f[2]), "=r"(f[3]) : "r"(a));
}
__device__ __forceinline__ void ldmB4(uint32_t base, int n_base, int kb,
                                      int lane, uint32_t* f) {
    int q = lane >> 3;
    int n = n_base + (q >> 1) * 8 + (lane & 7);
    int kk = kb + (q & 1) * 16;
    uint32_t a = base + swz((uint32_t)(n * 128 + kk));
    asm volatile("ldmatrix.sync.aligned.m8n8.x4.shared.b16 {%0,%1,%2,%3}, [%4];"
                 : "=r"(f[0]), "=r"(f[1]), "=r"(f[2]), "=r"(f[3]) : "r"(a));
}
// fp16-accumulator MMA (2x b32 accum)
__device__ __forceinline__ void mma_f16h(uint32_t* c, const uint32_t* a,
                                         const uint32_t* b) {
    asm volatile(
        "mma.sync.aligned.m16n8k16.row.col.f16.f16.f16.f16 "
        "{%0,%1},{%2,%3,%4,%5},{%6,%7},{%0,%1};"
        : "+r"(c[0]), "+r"(c[1])
        : "r"(a[0]), "r"(a[1]), "r"(a[2]), "r"(a[3]), "r"(b[0]), "r"(b[1]));
}
__device__ __forceinline__ float warp_sum(float s) {
#pragma unroll
    for (int o = 16; o; o >>= 1) s += __shfl_xor_sync(0xFFFFFFFFu, s, o);
    return s;
}
__device__ __forceinline__ unsigned long long umin64(unsigned long long a,
                                                     unsigned long long b) {
    return a < b ? a : b;
}
__device__ __forceinline__ void fold_min(unsigned long long& best, float xn,
                                         float yn, float dot, int col) {
    float d = fmaxf(fmaf(-2.f, dot, xn + yn), 0.f);
    unsigned long long p =
        ((unsigned long long)__float_as_uint(d) << 32) | (unsigned)col;
    best = umin64(best, p);
}

// ---------------- prep (3 launches keep gemm at profile index 3) ----------
__global__ void prep_E_kernel(const float* __restrict__ E) {
    int warp = (blockIdx.x * blockDim.x + threadIdx.x) >> 5;
    int lane = threadIdx.x & 31;
    if (warp >= N_ROWS) return;
    const float4* p =
        reinterpret_cast<const float4*>(E + (size_t)warp * DIM + lane * 12);
    __half2* dst =
        reinterpret_cast<__half2*>(g_Eh + (size_t)warp * DIM + lane * 12);
    float s = 0.f;
#pragma unroll
    for (int v = 0; v < 3; v++) {
        float4 f = p[v];
        s += f.x * f.x + f.y * f.y + f.z * f.z + f.w * f.w;
        dst[v * 2]     = __floats2half2_rn(f.x, f.y);
        dst[v * 2 + 1] = __floats2half2_rn(f.z, f.w);
    }
    s = warp_sum(s);
    if (!lane) { g_xnorm[warp] = s; g_packed[warp] = 0xFFFFFFFFFFFFFFFFull; }
}

__global__ void prep_B_kernel(const float* __restrict__ MB, int row_base) {
    int warp = (blockIdx.x * blockDim.x + threadIdx.x) >> 5;
    int lane = threadIdx.x & 31;
    int row = row_base + warp;
    if (warp >= M_BANK / 2) return;
    const float4* p =
        reinterpret_cast<const float4*>(MB + (size_t)row * DIM + lane * 12);
    __half2* dst =
        reinterpret_cast<__half2*>(g_Bh + (size_t)row * DIM + lane * 12);
    float s = 0.f;
#pragma unroll
    for (int v = 0; v < 3; v++) {
        float4 f = p[v];
        s += f.x * f.x + f.y * f.y + f.z * f.z + f.w * f.w;
        dst[v * 2]     = __floats2half2_rn(f.x, f.y);
        dst[v * 2 + 1] = __floats2half2_rn(f.z, f.w);
    }
    s = warp_sum(s);
    if (!lane) g_ynorm[row] = s;
}

// ---------------- B chunk loader ----------------
__device__ __forceinline__ void load_B(uint32_t sb, int c, int jt0, int t) {
    const int j0  = (jt0 + c / NCHUNK_K) * BN;
    const int kof = (c % NCHUNK_K) * BK;
    uint32_t sbase = sb + OFF_B + (c & 1) * B_STAGE_BYTES;
#pragma unroll
    for (int i = t; i < BN * 8; i += NTHR) {
        int r = i >> 3, g = i & 7;
        uint32_t d = swz((uint32_t)(r * 128 + g * 16));
        cp16(sbase + d, g_Bh + (size_t)(j0 + r) * DIM + kof + g * 8);
    }
}

// ---------------- main GEMM + fused min/argmin (2 CTAs/SM) ----------------
__global__ __launch_bounds__(NTHR, 2) void gemm_mma_kernel() {
    extern __shared__ __align__(1024) char smem[];
    uint32_t sb = smem_u32(smem);

    const int t = threadIdx.x;
    const int w = t >> 5, lane = t & 31;
    const int gid = lane >> 2, tig = lane & 3;
    const int wm = w & 1, wn = w >> 1;     // warp tile: rows wm*32, cols wn*64
    const int row0 = blockIdx.x * BM;
    const int jt0 = blockIdx.y * 43;
    const int jt1 = (jt0 + 43 < JT_TOTAL) ? jt0 + 43 : JT_TOTAL;
    const int TOT = (jt1 - jt0) * NCHUNK_K;

    // 4 rows per thread: wm*32 + {gid, gid+8, gid+16, gid+24}
    float xn[4];
#pragma unroll
    for (int r = 0; r < 4; r++)
        xn[r] = g_xnorm[row0 + wm * 32 + r * 8 + gid];

    unsigned long long best[4];
#pragma unroll
    for (int r = 0; r < 4; r++) best[r] = 0xFFFFFFFFFFFFFFFFull;

    // prologue: A strip resident (48 KB, once), then B chunk 0
#pragma unroll
    for (int ak = 0; ak < NCHUNK_K; ak++) {
        for (int i = t; i < BM * 8; i += NTHR) {
            int r = i >> 3, g = i & 7;
            uint32_t d = swz((uint32_t)(r * 128 + g * 16));
            cp16(sb + ak * A_CHUNK_BYTES + d,
                 g_Eh + (size_t)(row0 + r) * DIM + ak * BK + g * 8);
        }
    }
    CP_COMMIT();
    load_B(sb, 0, jt0, t);
    CP_COMMIT();

    uint32_t acc[2][8][2];     // [row atom][col atom][accum pair]
#pragma unroll
    for (int i = 0; i < 2; i++)
#pragma unroll
        for (int j = 0; j < 8; j++)
            acc[i][j][0] = acc[i][j][1] = 0u;

    for (int c = 0; c < TOT; c++) {
        CP_WAIT0();            // B_c (and A at c=0) resident
        __syncthreads();       // stage (c+1)&1 free
        if (c + 1 < TOT) { load_B(sb, c + 1, jt0, t); CP_COMMIT(); }

        const int ck = c % NCHUNK_K;
        const uint32_t sA = sb + ck * A_CHUNK_BYTES;
        const uint32_t sB = sb + OFF_B + (c & 1) * B_STAGE_BYTES;

#pragma unroll
        for (int kk = 0; kk < BK / 16; kk++) {
            const int kb = kk * 32;   // bytes
            uint32_t Af[2][4], Bf[8][2];
#pragma unroll
            for (int jj = 0; jj < 4; jj++) {
                uint32_t f[4];
                ldmB4(sB, wn * 64 + jj * 16, kb, lane, f);
                Bf[2 * jj][0] = f[0]; Bf[2 * jj][1] = f[1];
                Bf[2 * jj + 1][0] = f[2]; Bf[2 * jj + 1][1] = f[3];
            }
#pragma unroll
            for (int i = 0; i < 2; i++)
                ldmA(sA, wm * 32 + i * 16, kb, lane, Af[i]);
#pragma unroll
            for (int i = 0; i < 2; i++)
#pragma unroll
                for (int j = 0; j < 8; j++)
                    mma_f16h(acc[i][j], Af[i], Bf[j]);
        }

        if (ck == NCHUNK_K - 1) {
            const int j0 = (jt0 + c / NCHUNK_K) * BN;
#pragma unroll
            for (int j = 0; j < 8; j++) {
                int col = j0 + wn * 64 + j * 8 + tig * 2;
                float yn0 = g_ynorm[col], yn1 = g_ynorm[col + 1];
#pragma unroll
                for (int i = 0; i < 2; i++) {
                    float2 lo = __half22float2(
                        *reinterpret_cast<__half2*>(&acc[i][j][0]));
                    float2 hi = __half22float2(
                        *reinterpret_cast<__half2*>(&acc[i][j][1]));
                    fold_min(best[2 * i], xn[2 * i], yn0, lo.x, col);
                    fold_min(best[2 * i], xn[2 * i], yn1, lo.y, col + 1);
                    fold_min(best[2 * i + 1], xn[2 * i + 1], yn0, hi.x, col);
                    fold_min(best[2 * i + 1], xn[2 * i + 1], yn1, hi.y, col + 1);
                    acc[i][j][0] = acc[i][j][1] = 0u;
                }
            }
        }
    }

    // reduce across tig lanes (same rows), then spread-address atomicMin
#pragma unroll
    for (int r = 0; r < 4; r++) {
#pragma unroll
        for (int off = 1; off <= 2; off <<= 1)
            best[r] = umin64(best[r], __shfl_xor_sync(0xFFFFFFFFu, best[r], off));
    }
    if (tig == 0) {
#pragma unroll
        for (int r = 0; r < 4; r++)
            atomicMin(&g_packed[row0 + wm * 32 + r * 8 + gid], best[r]);
    }
}

// ---------------- tail: batch argmax + patch map write (fused) ----------------
__global__ void batch_map_kernel(float* __restrict__ out) {
    int b = blockIdx.x, t = threadIdx.x;
    __shared__ float sv[256];
    __shared__ int   si[256];
    float bv = -1.f; int bi = PATCHES;
    for (int p = t; p < PATCHES; p += 256) {
        unsigned long long pk = g_packed[b * PATCHES + p];
        float d = __uint_as_float((unsigned)(pk >> 32));
        out[b * PATCHES + p] = sqrtf(d);
        if (d > bv || (d == bv && p < bi)) { bv = d; bi = p; }
    }
    sv[t] = bv; si[t] = bi;
    __syncthreads();
    for (int s = 128; s; s >>= 1) {
        if (t < s) {
            if (sv[t + s] > sv[t] || (sv[t + s] == sv[t] && si[t + s] < si[t])) {
                sv[t] = sv[t + s]; si[t] = si[t + s];
            }
        }
        __syncthreads();
    }
    if (t == 0) {
        int row = b * PATCHES + si[0];
        unsigned long long pk = g_packed[row];
        g_maxrow[b] = row;
        g_score[b]  = sqrtf(__uint_as_float((unsigned)(pk >> 32)));
        g_nnidx[b]  = (int)(pk & 0xFFFFFFFFull);
    }
}

// ---------------- d2: 64 m-rows per block ----------------
__global__ void d2_block_kernel(const float* __restrict__ MB) {
    __shared__ float4 nn4[B_SZ][DIM / 4];
    __shared__ float  nyn[B_SZ];
    int t = threadIdx.x, wid = t >> 5, lane = t & 31;
    for (int i = t; i < B_SZ * (DIM / 4); i += 256) {
        int b = i / (DIM / 4), v = i % (DIM / 4);
        nn4[b][v] = reinterpret_cast<const float4*>(
            MB + (size_t)g_nnidx[b] * DIM)[v];
    }
    if (t < B_SZ) nyn[t] = g_ynorm[g_nnidx[t]];
    __syncthreads();

    int m0 = blockIdx.x * 64 + wid * 8;
#pragma unroll
    for (int mi = 0; mi < 8; mi++) {
        int m = m0 + mi;
        const float4* pm4 = reinterpret_cast<const float4*>(MB + (size_t)m * DIM);
        float s[B_SZ];
#pragma unroll
        for (int b = 0; b < B_SZ; b++) s[b] = 0.f;
#pragma unroll
        for (int v = 0; v < 3; v++) {
            float4 f = pm4[lane + v * 32];
#pragma unroll
            for (int b = 0; b < B_SZ; b++) {
                float4 g = nn4[b][lane + v * 32];
                s[b] += f.x * g.x + f.y * g.y + f.z * g.z + f.w * g.w;
            }
        }
#pragma unroll
        for (int b = 0; b < B_SZ; b++) s[b] = warp_sum(s[b]);
        if (lane == 0) {
            float ym = g_ynorm[m];
#pragma unroll
            for (int b = 0; b < B_SZ; b++)
                g_d2[b * M_BANK + m] = fmaxf(nyn[b] + ym - 2.f * s[b], 0.f);
        }
    }
}

// ---------------- top-9 stage A: shfl-reduce rounds ----------
__global__ void topkA_kernel() {
    __shared__ unsigned long long vals[SEG_LEN];
    __shared__ unsigned long long wred[8];
    int b = blockIdx.y, seg = blockIdx.x, t = threadIdx.x;
    int wid = t >> 5, lane = t & 31;
    for (int i = t; i < SEG_LEN; i += 256) {
        int m = seg * SEG_LEN + i;
        vals[i] = ((unsigned long long)__float_as_uint(g_d2[b * M_BANK + m]) << 32)
                  | (unsigned)m;
    }
    __syncthreads();
    for (int r = 0; r < KNN; r++) {
        unsigned long long mv = umin64(umin64(vals[t], vals[t + 256]),
                                       umin64(vals[t + 512], vals[t + 768]));
#pragma unroll
        for (int off = 16; off; off >>= 1)
            mv = umin64(mv, __shfl_xor_sync(0xFFFFFFFFu, mv, off));
        if (!lane) wred[wid] = mv;
        __syncthreads();
        if (t == 0) {
            unsigned long long m = wred[0];
#pragma unroll
            for (int i = 1; i < 8; i++) m = umin64(m, wred[i]);
            g_part[(b * SEGS + seg) * KNN + r] = m;
            vals[(unsigned)m - seg * SEG_LEN] = 0xFFFFFFFFFFFFFFFFull;
        }
        __syncthreads();
    }
}

// ---------------- top-9 merge + final score (fused) ----------------
__global__ void topk_final_kernel(const float* __restrict__ E,
                                  const float* __restrict__ MB,
                                  float* __restrict__ out) {
    __shared__ unsigned long long cand[512];
    __shared__ unsigned long long red[512];
    __shared__ int   sup[KNN];
    __shared__ float d3[KNN];
    int b = blockIdx.x, t = threadIdx.x;
    cand[t] = (t < SEGS * KNN) ? g_part[b * SEGS * KNN + t]
                               : 0xFFFFFFFFFFFFFFFFull;
    __syncthreads();
    for (int r = 0; r < KNN; r++) {
        red[t] = cand[t];
        __syncthreads();
        for (int s = 256; s; s >>= 1) {
            if (t < s) red[t] = umin64(red[t], red[t + s]);
            __syncthreads();
        }
        unsigned long long sel = red[0];
        if (t == 0) sup[r] = (int)(sel & 0xFFFFFFFFull);
        if (cand[t] == sel) cand[t] = 0xFFFFFFFFFFFFFFFFull;
        __syncthreads();
    }

    int wid = t >> 5, lane = t & 31;
    int row = g_maxrow[b];
    if (wid < KNN) {
        const float* xf = E + (size_t)row * DIM;
        int sp = sup[wid];
        const float* pv = MB + (size_t)sp * DIM;
        float s = 0.f;
        for (int k = lane; k < DIM; k += 32) s += xf[k] * pv[k];
        s = warp_sum(s);
        if (!lane)
            d3[wid] = sqrtf(fmaxf(g_xnorm[row] + g_ynorm[sp] - 2.f * s, 0.f));
    }
    __syncthreads();
    if (t == 0) {
        float mx = -FLT_MAX;
        for (int j = 0; j < KNN; j++) mx = fmaxf(mx, d3[j]);
        float den = 0.f, e0 = 0.f;
        for (int j = 0; j < KNN; j++) {
            float e = expf(d3[j] - mx);
            den += e;
            if (j == 0) e0 = e;
        }
        out[N_ROWS + b] = (1.f - e0 / den) * g_score[b];
    }
}

// ---------------- launch ----------------
extern "C" void kernel_launch(void* const* d_in, const int* in_sizes, int n_in,
                              void* d_out, int out_size) {
    (void)n_in; (void)in_sizes; (void)out_size;
    const float* E  = (const float*)d_in[0];
    const float* MB = (const float*)d_in[1];
    float* out = (float*)d_out;

    cudaFuncSetAttribute(gemm_mma_kernel,
                         cudaFuncAttributeMaxDynamicSharedMemorySize, SMEM_BYTES);

    // 3 prep launches keep gemm at profile index 3
    prep_E_kernel<<<(N_ROWS * 32 + 255) / 256, 256>>>(E);
    prep_B_kernel<<<(M_BANK / 2 * 32 + 255) / 256, 256>>>(MB, 0);
    prep_B_kernel<<<(M_BANK / 2 * 32 + 255) / 256, 256>>>(MB, M_BANK / 2);

    gemm_mma_kernel<<<dim3(ROW_TILES, GRID_Y), NTHR, SMEM_BYTES>>>();

    batch_map_kernel<<<B_SZ, 256>>>(out);
    d2_block_kernel<<<M_BANK / 64, 256>>>(MB);
    topkA_kernel<<<dim3(SEGS, B_SZ), 256>>>();
    topk_final_kernel<<<B_SZ, 512>>>(E, MB, out);
}

// round 16
// speedup vs baseline: 1.0455x; 1.0455x over previous
#include <cuda_runtime.h>
#include <cuda_fp16.h>
#include <float.h>
#include <stdint.h>

// ---------------- problem constants ----------------
constexpr int N_ROWS  = 6272;
constexpr int M_BANK  = 32768;
constexpr int DIM     = 384;
constexpr int B_SZ    = 8;
constexpr int PATCHES = N_ROWS / B_SZ;
constexpr int KNN     = 9;

// ---------------- GEMM tiling (R13 config — best measured, 402us) ----------------
constexpr int BM = 128;
constexpr int BN = 256;
constexpr int BK = 128;                // K chunk; stored as 2x 128B-row halves
constexpr int NCHUNK_K = DIM / BK;     // 3
constexpr int JT_TOTAL = M_BANK / BN;  // 128
constexpr int GRID_Y   = 3;            // 147 CTAs = 1 wave
constexpr int ROW_TILES = N_ROWS / BM; // 49
constexpr int NTHR = 256;              // 8 warps

constexpr int A_CHUNK_BYTES = BM * 128;                   // 16384
constexpr int OFF_B         = 6 * A_CHUNK_BYTES;          // 98304
constexpr int B_STAGE_BYTES = BN * 256;                   // 65536
constexpr int YN_OFF        = OFF_B + 2 * B_STAGE_BYTES;  // 229376
constexpr int SMEM_BYTES    = YN_OFF + 2048;              // 231424

// top-k staging
constexpr int SEGS = 32;
constexpr int SEG_LEN = M_BANK / SEGS;  // 1024

// ---------------- device scratch ----------------
__device__ __align__(256) __half g_Eh[N_ROWS * DIM];
__device__ __align__(256) __half g_Bh[M_BANK * DIM];
__device__ float              g_xnorm[N_ROWS];
__device__ float              g_ynorm[M_BANK];
__device__ unsigned long long g_packed[N_ROWS];
__device__ float              g_d2[B_SZ * M_BANK];
__device__ unsigned long long g_part[B_SZ * SEGS * KNN];
__device__ int                g_maxrow[B_SZ];
__device__ float              g_score[B_SZ];
__device__ int                g_nnidx[B_SZ];

// ---------------- helpers ----------------
__device__ __forceinline__ uint32_t smem_u32(const void* p) {
    uint32_t a;
    asm("{ .reg .u64 t; cvta.to.shared.u64 t, %1; cvt.u32.u64 %0, t; }"
        : "=r"(a) : "l"(p));
    return a;
}
__device__ __forceinline__ void cp16(uint32_t dst, const void* src) {
    asm volatile("cp.async.cg.shared.global [%0], [%1], 16;"
                 :: "r"(dst), "l"(src) : "memory");
}
#define CP_COMMIT() asm volatile("cp.async.commit_group;" ::: "memory")
#define CP_WAIT0()  asm volatile("cp.async.wait_group 0;" ::: "memory")

__device__ __forceinline__ uint32_t swz(uint32_t o) { return o ^ ((o >> 3) & 0x70); }

__device__ __forceinline__ void ldmA(uint32_t base, int r_base, int kb,
                                     int lane, uint32_t* f) {
    int q = lane >> 3;
    int r = r_base + (q & 1) * 8 + (lane & 7);
    int kk = kb + (q >> 1) * 16;
    uint32_t a = base + swz((uint32_t)(r * 128 + kk));
    asm volatile("ldmatrix.sync.aligned.m8n8.x4.shared.b16 {%0,%1,%2,%3}, [%4];"
                 : "=r"(f[0]), "=r"(f[1]), "=r"(f[2]), "=r"(f[3]) : "r"(a));
}
__device__ __forceinline__ void ldmB4(uint32_t base, int n_base, int kb,
                                      int lane, uint32_t* f) {
    int q = lane >> 3;
    int n = n_base + (q >> 1) * 8 + (lane & 7);
    int kk = kb + (q & 1) * 16;
    uint32_t a = base + swz((uint32_t)(n * 128 + kk));
    asm volatile("ldmatrix.sync.aligned.m8n8.x4.shared.b16 {%0,%1,%2,%3}, [%4];"
                 : "=r"(f[0]), "=r"(f[1]), "=r"(f[2]), "=r"(f[3]) : "r"(a));
}
__device__ __forceinline__ void mma_f16(float* c, const uint32_t* a,
                                        const uint32_t* b) {
    asm volatile(
        "mma.sync.aligned.m16n8k16.row.col.f32.f16.f16.f32 "
        "{%0,%1,%2,%3},{%4,%5,%6,%7},{%8,%9},{%0,%1,%2,%3};"
        : "+f"(c[0]), "+f"(c[1]), "+f"(c[2]), "+f"(c[3])
        : "r"(a[0]), "r"(a[1]), "r"(a[2]), "r"(a[3]), "r"(b[0]), "r"(b[1]));
}
__device__ __forceinline__ float warp_sum(float s) {
#pragma unroll
    for (int o = 16; o; o >>= 1) s += __shfl_xor_sync(0xFFFFFFFFu, s, o);
    return s;
}
__device__ __forceinline__ unsigned long long umin64(unsigned long long a,
                                                     unsigned long long b) {
    return a < b ? a : b;
}
__device__ __forceinline__ void fold_min(unsigned long long& best, float xn,
                                         float yn, float dot, int col) {
    float d = fmaxf(fmaf(-2.f, dot, xn + yn), 0.f);
    unsigned long long p =
        ((unsigned long long)__float_as_uint(d) << 32) | (unsigned)col;
    best = umin64(best, p);
}

// ---------------- fused prep: fp16 convert + norms + packed init (1 launch) ----
__global__ void prep_all_kernel(const float* __restrict__ E,
                                const float* __restrict__ MB) {
    int warp = (blockIdx.x * blockDim.x + threadIdx.x) >> 5;
    int lane = threadIdx.x & 31;
    if (warp >= N_ROWS + M_BANK) return;
    bool isE = warp < N_ROWS;
    int row = isE ? warp : warp - N_ROWS;
    const float* src = isE ? E : MB;
    __half* dsth = isE ? g_Eh : g_Bh;
    const float4* p =
        reinterpret_cast<const float4*>(src + (size_t)row * DIM + lane * 12);
    __half2* dst =
        reinterpret_cast<__half2*>(dsth + (size_t)row * DIM + lane * 12);
    float s = 0.f;
#pragma unroll
    for (int v = 0; v < 3; v++) {
        float4 f = p[v];
        s += f.x * f.x + f.y * f.y + f.z * f.z + f.w * f.w;
        dst[v * 2]     = __floats2half2_rn(f.x, f.y);
        dst[v * 2 + 1] = __floats2half2_rn(f.z, f.w);
    }
    s = warp_sum(s);
    if (!lane) {
        if (isE) { g_xnorm[row] = s; g_packed[row] = 0xFFFFFFFFFFFFFFFFull; }
        else     g_ynorm[row] = s;
    }
}

// ---------------- B chunk (+ per-tile ynorm) loader ----------------
__device__ __forceinline__ void load_B(uint32_t sb, int c, int jt0, int t) {
    const int tl  = c / NCHUNK_K;
    const int j0  = (jt0 + tl) * BN;
    const int kof = (c % NCHUNK_K) * BK;
    uint32_t sbase = sb + OFF_B + (c & 1) * B_STAGE_BYTES;
#pragma unroll
    for (int i = t; i < BN * 16; i += NTHR) {
        int r = i >> 4, g = i & 15, h = g >> 3, gg = g & 7;
        uint32_t d = h * 32768 + swz((uint32_t)(r * 128 + gg * 16));
        cp16(sbase + d, g_Bh + (size_t)(j0 + r) * DIM + kof + h * 64 + gg * 8);
    }
    if ((c % NCHUNK_K) == 0 && t < 64)
        cp16(sb + YN_OFF + (tl & 1) * 1024 + t * 16, g_ynorm + j0 + t * 4);
}

// ---------------- main GEMM + fused min/argmin (R13 verbatim) ----------------
__global__ __launch_bounds__(NTHR) void gemm_mma_kernel() {
    extern __shared__ __align__(1024) char smem[];
    uint32_t sb = smem_u32(smem);
    const float* ynbuf = (const float*)(smem + YN_OFF);
    unsigned long long* red = (unsigned long long*)(smem + YN_OFF);

    const int t = threadIdx.x;
    const int w = t >> 5, lane = t & 31;
    const int gid = lane >> 2, tig = lane & 3;
    const int wm = w & 1, wn = w >> 1;     // warp tile: rows wm*64, cols wn*64
    const int row0 = blockIdx.x * BM;
    const int jt0 = blockIdx.y * 43;
    const int jt1 = (jt0 + 43 < JT_TOTAL) ? jt0 + 43 : JT_TOTAL;
    const int TOT = (jt1 - jt0) * NCHUNK_K;

    float xnA[4], xnB[4];
#pragma unroll
    for (int i = 0; i < 4; i++) {
        xnA[i] = g_xnorm[row0 + wm * 64 + i * 16 + gid];
        xnB[i] = g_xnorm[row0 + wm * 64 + i * 16 + gid + 8];
    }

    unsigned long long bestA[4], bestB[4];
#pragma unroll
    for (int i = 0; i < 4; i++) bestA[i] = bestB[i] = 0xFFFFFFFFFFFFFFFFull;

    // prologue: A full-K resident (6 x 16KB sub-chunks), then B chunk 0
#pragma unroll
    for (int ak = 0; ak < 6; ak++) {
        for (int i = t; i < BM * 8; i += NTHR) {
            int r = i >> 3, g = i & 7;
            uint32_t d = swz((uint32_t)(r * 128 + g * 16));
            cp16(sb + ak * A_CHUNK_BYTES + d,
                 g_Eh + (size_t)(row0 + r) * DIM + ak * 64 + g * 8);
        }
    }
    CP_COMMIT();
    load_B(sb, 0, jt0, t);
    CP_COMMIT();

    float acc[4][8][4];
#pragma unroll
    for (int i = 0; i < 4; i++)
#pragma unroll
        for (int j = 0; j < 8; j++)
#pragma unroll
            for (int q = 0; q < 4; q++) acc[i][j][q] = 0.f;

    for (int c = 0; c < TOT; c++) {
        CP_WAIT0();            // B_c (and A at c=0, ynorm) resident
        __syncthreads();       // all warps done with chunk c-1 -> stage free
        if (c + 1 < TOT) { load_B(sb, c + 1, jt0, t); CP_COMMIT(); }

        const int ck = c % NCHUNK_K;
        const uint32_t sB = sb + OFF_B + (c & 1) * B_STAGE_BYTES;

#pragma unroll
        for (int kk = 0; kk < 8; kk++) {           // BK=128 -> 8 k16 steps
            const int kb = (kk & 3) * 32;          // bytes within 128B row
            const uint32_t sA = sb + (ck * 2 + (kk >> 2)) * A_CHUNK_BYTES;
            const uint32_t sBh = sB + (kk >> 2) * 32768;
            uint32_t Af[4][4], Bf[8][2];
#pragma unroll
            for (int jj = 0; jj < 4; jj++) {
                uint32_t f[4];
                ldmB4(sBh, wn * 64 + jj * 16, kb, lane, f);
                Bf[2 * jj][0] = f[0]; Bf[2 * jj][1] = f[1];
                Bf[2 * jj + 1][0] = f[2]; Bf[2 * jj + 1][1] = f[3];
            }
#pragma unroll
            for (int i = 0; i < 4; i++)
                ldmA(sA, wm * 64 + i * 16, kb, lane, Af[i]);
#pragma unroll
            for (int i = 0; i < 4; i++)
#pragma unroll
                for (int j = 0; j < 8; j++)
                    mma_f16(acc[i][j], Af[i], Bf[j]);
        }

        if (ck == NCHUNK_K - 1) {
            const int tl = c / NCHUNK_K;
            const int j0 = (jt0 + tl) * BN;
            const float* yn = ynbuf + (tl & 1) * 256;
#pragma unroll
            for (int i = 0; i < 4; i++)
#pragma unroll
                for (int j = 0; j < 8; j++) {
                    int cl = wn * 64 + j * 8 + tig * 2;
                    float yn0 = yn[cl], yn1 = yn[cl + 1];
                    int col = j0 + cl;
                    fold_min(bestA[i], xnA[i], yn0, acc[i][j][0], col);
                    fold_min(bestA[i], xnA[i], yn1, acc[i][j][1], col + 1);
                    fold_min(bestB[i], xnB[i], yn0, acc[i][j][2], col);
                    fold_min(bestB[i], xnB[i], yn1, acc[i][j][3], col + 1);
                    acc[i][j][0] = acc[i][j][1] = acc[i][j][2] = acc[i][j][3] = 0.f;
                }
        }
    }

    // reduce across tig lanes (same row)
#pragma unroll
    for (int i = 0; i < 4; i++) {
#pragma unroll
        for (int off = 1; off <= 2; off <<= 1) {
            bestA[i] = umin64(bestA[i], __shfl_xor_sync(0xFFFFFFFFu, bestA[i], off));
            bestB[i] = umin64(bestB[i], __shfl_xor_sync(0xFFFFFFFFu, bestB[i], off));
        }
    }

    __syncthreads();   // ynorm slots dead; reuse region as reduce buffer
    if (t < BM) red[t] = 0xFFFFFFFFFFFFFFFFull;
    __syncthreads();
    if (tig == 0) {
#pragma unroll
        for (int i = 0; i < 4; i++) {
            atomicMin(&red[wm * 64 + i * 16 + gid], bestA[i]);
            atomicMin(&red[wm * 64 + i * 16 + gid + 8], bestB[i]);
        }
    }
    __syncthreads();
    if (t < BM) atomicMin(&g_packed[row0 + t], red[t]);
}

// ---------------- tail: batch argmax + patch map write (fused) ----------------
__global__ void batch_map_kernel(float* __restrict__ out) {
    int b = blockIdx.x, t = threadIdx.x;
    __shared__ float sv[256];
    __shared__ int   si[256];
    float bv = -1.f; int bi = PATCHES;
    for (int p = t; p < PATCHES; p += 256) {
        unsigned long long pk = g_packed[b * PATCHES + p];
        float d = __uint_as_float((unsigned)(pk >> 32));
        out[b * PATCHES + p] = sqrtf(d);
        if (d > bv || (d == bv && p < bi)) { bv = d; bi = p; }
    }
    sv[t] = bv; si[t] = bi;
    __syncthreads();
    for (int s = 128; s; s >>= 1) {
        if (t < s) {
            if (sv[t + s] > sv[t] || (sv[t + s] == sv[t] && si[t + s] < si[t])) {
                sv[t] = sv[t + s]; si[t] = si[t + s];
            }
        }
        __syncthreads();
    }
    if (t == 0) {
        int row = b * PATCHES + si[0];
        unsigned long long pk = g_packed[row];
        g_maxrow[b] = row;
        g_score[b]  = sqrtf(__uint_as_float((unsigned)(pk >> 32)));
        g_nnidx[b]  = (int)(pk & 0xFFFFFFFFull);
    }
}

// ---------------- d2: 64 m-rows per block (nn reload amortized 8x) ----------------
__global__ void d2_block_kernel(const float* __restrict__ MB) {
    __shared__ float4 nn4[B_SZ][DIM / 4];   // 12 KB
    __shared__ float  nyn[B_SZ];
    int t = threadIdx.x, wid = t >> 5, lane = t & 31;
    for (int i = t; i < B_SZ * (DIM / 4); i += 256) {
        int b = i / (DIM / 4), v = i % (DIM / 4);
        nn4[b][v] = reinterpret_cast<const float4*>(
            MB + (size_t)g_nnidx[b] * DIM)[v];
    }
    if (t < B_SZ) nyn[t] = g_ynorm[g_nnidx[t]];
    __syncthreads();

    int m0 = blockIdx.x * 64 + wid * 8;
#pragma unroll
    for (int mi = 0; mi < 8; mi++) {
        int m = m0 + mi;
        const float4* pm4 = reinterpret_cast<const float4*>(MB + (size_t)m * DIM);
        float s[B_SZ];
#pragma unroll
        for (int b = 0; b < B_SZ; b++) s[b] = 0.f;
#pragma unroll
        for (int v = 0; v < 3; v++) {
            float4 f = pm4[lane + v * 32];
#pragma unroll
            for (int b = 0; b < B_SZ; b++) {
                float4 g = nn4[b][lane + v * 32];
                s[b] += f.x * g.x + f.y * g.y + f.z * g.z + f.w * g.w;
            }
        }
#pragma unroll
        for (int b = 0; b < B_SZ; b++) s[b] = warp_sum(s[b]);
        if (lane == 0) {
            float ym = g_ynorm[m];
#pragma unroll
            for (int b = 0; b < B_SZ; b++)
                g_d2[b * M_BANK + m] = fmaxf(nyn[b] + ym - 2.f * s[b], 0.f);
        }
    }
}

// ---------------- top-9 stage A: shfl-reduce rounds ----------
__global__ void topkA_kernel() {
    __shared__ unsigned long long vals[SEG_LEN];
    __shared__ unsigned long long wred[8];
    int b = blockIdx.y, seg = blockIdx.x, t = threadIdx.x;
    int wid = t >> 5, lane = t & 31;
    for (int i = t; i < SEG_LEN; i += 256) {
        int m = seg * SEG_LEN + i;
        vals[i] = ((unsigned long long)__float_as_uint(g_d2[b * M_BANK + m]) << 32)
                  | (unsigned)m;
    }
    __syncthreads();
    for (int r = 0; r < KNN; r++) {
        unsigned long long mv = umin64(umin64(vals[t], vals[t + 256]),
                                       umin64(vals[t + 512], vals[t + 768]));
#pragma unroll
        for (int off = 16; off; off >>= 1)
            mv = umin64(mv, __shfl_xor_sync(0xFFFFFFFFu, mv, off));
        if (!lane) wred[wid] = mv;
        __syncthreads();
        if (t == 0) {
            unsigned long long m = wred[0];
#pragma unroll
            for (int i = 1; i < 8; i++) m = umin64(m, wred[i]);
            g_part[(b * SEGS + seg) * KNN + r] = m;
            vals[(unsigned)m - seg * SEG_LEN] = 0xFFFFFFFFFFFFFFFFull;
        }
        __syncthreads();
    }
}

// ---------------- top-9 merge + final score (fused) ----------------
__global__ void topk_final_kernel(const float* __restrict__ E,
                                  const float* __restrict__ MB,
                                  float* __restrict__ out) {
    __shared__ unsigned long long cand[512];
    __shared__ unsigned long long red[512];
    __shared__ int   sup[KNN];
    __shared__ float d3[KNN];
    int b = blockIdx.x, t = threadIdx.x;
    cand[t] = (t < SEGS * KNN) ? g_part[b * SEGS * KNN + t]
                               : 0xFFFFFFFFFFFFFFFFull;
    __syncthreads();
    for (int r = 0; r < KNN; r++) {
        red[t] = cand[t];
        __syncthreads();
        for (int s = 256; s; s >>= 1) {
            if (t < s) red[t] = umin64(red[t], red[t + s]);
            __syncthreads();
        }
        unsigned long long sel = red[0];
        if (t == 0) sup[r] = (int)(sel & 0xFFFFFFFFull);
        if (cand[t] == sel) cand[t] = 0xFFFFFFFFFFFFFFFFull;
        __syncthreads();
    }

    int wid = t >> 5, lane = t & 31;
    int row = g_maxrow[b];
    if (wid < KNN) {
        const float* xf = E + (size_t)row * DIM;
        int sp = sup[wid];
        const float* pv = MB + (size_t)sp * DIM;
        float s = 0.f;
        for (int k = lane; k < DIM; k += 32) s += xf[k] * pv[k];
        s = warp_sum(s);
        if (!lane)
            d3[wid] = sqrtf(fmaxf(g_xnorm[row] + g_ynorm[sp] - 2.f * s, 0.f));
    }
    __syncthreads();
    if (t == 0) {
        float mx = -FLT_MAX;
        for (int j = 0; j < KNN; j++) mx = fmaxf(mx, d3[j]);
        float den = 0.f, e0 = 0.f;
        for (int j = 0; j < KNN; j++) {
            float e = expf(d3[j] - mx);
            den += e;
            if (j == 0) e0 = e;
        }
        out[N_ROWS + b] = (1.f - e0 / den) * g_score[b];
    }
}

// ---------------- launch ----------------
extern "C" void kernel_launch(void* const* d_in, const int* in_sizes, int n_in,
                              void* d_out, int out_size) {
    (void)n_in; (void)in_sizes; (void)out_size;
    const float* E  = (const float*)d_in[0];
    const float* MB = (const float*)d_in[1];
    float* out = (float*)d_out;

    cudaFuncSetAttribute(gemm_mma_kernel,
                         cudaFuncAttributeMaxDynamicSharedMemorySize, SMEM_BYTES);

    int warps = N_ROWS + M_BANK;
    prep_all_kernel<<<(warps * 32 + 255) / 256, 256>>>(E, MB);

    gemm_mma_kernel<<<dim3(ROW_TILES, GRID_Y), NTHR, SMEM_BYTES>>>();

    batch_map_kernel<<<B_SZ, 256>>>(out);
    d2_block_kernel<<<M_BANK / 64, 256>>>(MB);
    topkA_kernel<<<dim3(SEGS, B_SZ), 256>>>();
    topk_final_kernel<<<B_SZ, 512>>>(E, MB, out);
}

// round 17
// speedup vs baseline: 1.0475x; 1.0019x over previous
#include <cuda_runtime.h>
#include <cuda_fp16.h>
#include <float.h>
#include <stdint.h>

// ---------------- problem constants ----------------
constexpr int N_ROWS  = 6272;
constexpr int M_BANK  = 32768;
constexpr int DIM     = 384;
constexpr int B_SZ    = 8;
constexpr int PATCHES = N_ROWS / B_SZ;
constexpr int KNN     = 9;

// ---------------- GEMM tiling (R13 config — best measured, 402us) ----------------
constexpr int BM = 128;
constexpr int BN = 256;
constexpr int BK = 128;                // K chunk; stored as 2x 128B-row halves
constexpr int NCHUNK_K = DIM / BK;     // 3
constexpr int JT_TOTAL = M_BANK / BN;  // 128
constexpr int GRID_Y   = 3;            // 147 CTAs = 1 wave
constexpr int ROW_TILES = N_ROWS / BM; // 49
constexpr int NTHR = 256;              // 8 warps

constexpr int A_CHUNK_BYTES = BM * 128;                   // 16384
constexpr int OFF_B         = 6 * A_CHUNK_BYTES;          // 98304
constexpr int B_STAGE_BYTES = BN * 256;                   // 65536
constexpr int YN_OFF        = OFF_B + 2 * B_STAGE_BYTES;  // 229376
constexpr int SMEM_BYTES    = YN_OFF + 2048;              // 231424

// top-k staging
constexpr int SEGS = 32;
constexpr int SEG_LEN = M_BANK / SEGS;  // 1024

// ---------------- device scratch ----------------
__device__ __align__(256) __half g_Eh[N_ROWS * DIM];
__device__ __align__(256) __half g_Bh[M_BANK * DIM];
__device__ float              g_xnorm[N_ROWS];
__device__ float              g_ynorm[M_BANK];
__device__ unsigned long long g_packed[N_ROWS];
__device__ float              g_d2[B_SZ * M_BANK];
__device__ unsigned long long g_part[B_SZ * SEGS * KNN];
__device__ int                g_maxrow[B_SZ];
__device__ float              g_score[B_SZ];
__device__ int                g_nnidx[B_SZ];

// ---------------- helpers ----------------
__device__ __forceinline__ uint32_t smem_u32(const void* p) {
    uint32_t a;
    asm("{ .reg .u64 t; cvta.to.shared.u64 t, %1; cvt.u32.u64 %0, t; }"
        : "=r"(a) : "l"(p));
    return a;
}
__device__ __forceinline__ void cp16(uint32_t dst, const void* src) {
    asm volatile("cp.async.cg.shared.global [%0], [%1], 16;"
                 :: "r"(dst), "l"(src) : "memory");
}
#define CP_COMMIT() asm volatile("cp.async.commit_group;" ::: "memory")
#define CP_WAIT0()  asm volatile("cp.async.wait_group 0;" ::: "memory")

__device__ __forceinline__ uint32_t swz(uint32_t o) { return o ^ ((o >> 3) & 0x70); }

__device__ __forceinline__ void ldmA(uint32_t base, int r_base, int kb,
                                     int lane, uint32_t* f) {
    int q = lane >> 3;
    int r = r_base + (q & 1) * 8 + (lane & 7);
    int kk = kb + (q >> 1) * 16;
    uint32_t a = base + swz((uint32_t)(r * 128 + kk));
    asm volatile("ldmatrix.sync.aligned.m8n8.x4.shared.b16 {%0,%1,%2,%3}, [%4];"
                 : "=r"(f[0]), "=r"(f[1]), "=r"(f[2]), "=r"(f[3]) : "r"(a));
}
__device__ __forceinline__ void ldmB4(uint32_t base, int n_base, int kb,
                                      int lane, uint32_t* f) {
    int q = lane >> 3;
    int n = n_base + (q >> 1) * 8 + (lane & 7);
    int kk = kb + (q & 1) * 16;
    uint32_t a = base + swz((uint32_t)(n * 128 + kk));
    asm volatile("ldmatrix.sync.aligned.m8n8.x4.shared.b16 {%0,%1,%2,%3}, [%4];"
                 : "=r"(f[0]), "=r"(f[1]), "=r"(f[2]), "=r"(f[3]) : "r"(a));
}
__device__ __forceinline__ void mma_f16(float* c, const uint32_t* a,
                                        const uint32_t* b) {
    asm volatile(
        "mma.sync.aligned.m16n8k16.row.col.f32.f16.f16.f32 "
        "{%0,%1,%2,%3},{%4,%5,%6,%7},{%8,%9},{%0,%1,%2,%3};"
        : "+f"(c[0]), "+f"(c[1]), "+f"(c[2]), "+f"(c[3])
        : "r"(a[0]), "r"(a[1]), "r"(a[2]), "r"(a[3]), "r"(b[0]), "r"(b[1]));
}
__device__ __forceinline__ float warp_sum(float s) {
#pragma unroll
    for (int o = 16; o; o >>= 1) s += __shfl_xor_sync(0xFFFFFFFFu, s, o);
    return s;
}
__device__ __forceinline__ unsigned long long umin64(unsigned long long a,
                                                     unsigned long long b) {
    return a < b ? a : b;
}
__device__ __forceinline__ void fold_min(unsigned long long& best, float xn,
                                         float yn, float dot, int col) {
    float d = fmaxf(fmaf(-2.f, dot, xn + yn), 0.f);
    unsigned long long p =
        ((unsigned long long)__float_as_uint(d) << 32) | (unsigned)col;
    best = umin64(best, p);
}

// ---------------- fused prep: fp16 convert + norms + packed init (1 launch) ----
__global__ void prep_all_kernel(const float* __restrict__ E,
                                const float* __restrict__ MB) {
    int warp = (blockIdx.x * blockDim.x + threadIdx.x) >> 5;
    int lane = threadIdx.x & 31;
    if (warp >= N_ROWS + M_BANK) return;
    bool isE = warp < N_ROWS;
    int row = isE ? warp : warp - N_ROWS;
    const float* src = isE ? E : MB;
    __half* dsth = isE ? g_Eh : g_Bh;
    const float4* p =
        reinterpret_cast<const float4*>(src + (size_t)row * DIM + lane * 12);
    __half2* dst =
        reinterpret_cast<__half2*>(dsth + (size_t)row * DIM + lane * 12);
    float s = 0.f;
#pragma unroll
    for (int v = 0; v < 3; v++) {
        float4 f = p[v];
        s += f.x * f.x + f.y * f.y + f.z * f.z + f.w * f.w;
        dst[v * 2]     = __floats2half2_rn(f.x, f.y);
        dst[v * 2 + 1] = __floats2half2_rn(f.z, f.w);
    }
    s = warp_sum(s);
    if (!lane) {
        if (isE) { g_xnorm[row] = s; g_packed[row] = 0xFFFFFFFFFFFFFFFFull; }
        else     g_ynorm[row] = s;
    }
}

// ---------------- B chunk (+ per-tile ynorm) loader ----------------
__device__ __forceinline__ void load_B(uint32_t sb, int c, int jt0, int t) {
    const int tl  = c / NCHUNK_K;
    const int j0  = (jt0 + tl) * BN;
    const int kof = (c % NCHUNK_K) * BK;
    uint32_t sbase = sb + OFF_B + (c & 1) * B_STAGE_BYTES;
#pragma unroll
    for (int i = t; i < BN * 16; i += NTHR) {
        int r = i >> 4, g = i & 15, h = g >> 3, gg = g & 7;
        uint32_t d = h * 32768 + swz((uint32_t)(r * 128 + gg * 16));
        cp16(sbase + d, g_Bh + (size_t)(j0 + r) * DIM + kof + h * 64 + gg * 8);
    }
    if ((c % NCHUNK_K) == 0 && t < 64)
        cp16(sb + YN_OFF + (tl & 1) * 1024 + t * 16, g_ynorm + j0 + t * 4);
}

// ---------------- main GEMM + fused min/argmin (R13 verbatim) ----------------
__global__ __launch_bounds__(NTHR) void gemm_mma_kernel() {
    extern __shared__ __align__(1024) char smem[];
    uint32_t sb = smem_u32(smem);
    const float* ynbuf = (const float*)(smem + YN_OFF);
    unsigned long long* red = (unsigned long long*)(smem + YN_OFF);

    const int t = threadIdx.x;
    const int w = t >> 5, lane = t & 31;
    const int gid = lane >> 2, tig = lane & 3;
    const int wm = w & 1, wn = w >> 1;     // warp tile: rows wm*64, cols wn*64
    const int row0 = blockIdx.x * BM;
    const int jt0 = blockIdx.y * 43;
    const int jt1 = (jt0 + 43 < JT_TOTAL) ? jt0 + 43 : JT_TOTAL;
    const int TOT = (jt1 - jt0) * NCHUNK_K;

    float xnA[4], xnB[4];
#pragma unroll
    for (int i = 0; i < 4; i++) {
        xnA[i] = g_xnorm[row0 + wm * 64 + i * 16 + gid];
        xnB[i] = g_xnorm[row0 + wm * 64 + i * 16 + gid + 8];
    }

    unsigned long long bestA[4], bestB[4];
#pragma unroll
    for (int i = 0; i < 4; i++) bestA[i] = bestB[i] = 0xFFFFFFFFFFFFFFFFull;

    // prologue: A full-K resident (6 x 16KB sub-chunks), then B chunk 0
#pragma unroll
    for (int ak = 0; ak < 6; ak++) {
        for (int i = t; i < BM * 8; i += NTHR) {
            int r = i >> 3, g = i & 7;
            uint32_t d = swz((uint32_t)(r * 128 + g * 16));
            cp16(sb + ak * A_CHUNK_BYTES + d,
                 g_Eh + (size_t)(row0 + r) * DIM + ak * 64 + g * 8);
        }
    }
    CP_COMMIT();
    load_B(sb, 0, jt0, t);
    CP_COMMIT();

    float acc[4][8][4];
#pragma unroll
    for (int i = 0; i < 4; i++)
#pragma unroll
        for (int j = 0; j < 8; j++)
#pragma unroll
            for (int q = 0; q < 4; q++) acc[i][j][q] = 0.f;

    for (int c = 0; c < TOT; c++) {
        CP_WAIT0();            // B_c (and A at c=0, ynorm) resident
        __syncthreads();       // all warps done with chunk c-1 -> stage free
        if (c + 1 < TOT) { load_B(sb, c + 1, jt0, t); CP_COMMIT(); }

        const int ck = c % NCHUNK_K;
        const uint32_t sB = sb + OFF_B + (c & 1) * B_STAGE_BYTES;

#pragma unroll
        for (int kk = 0; kk < 8; kk++) {           // BK=128 -> 8 k16 steps
            const int kb = (kk & 3) * 32;          // bytes within 128B row
            const uint32_t sA = sb + (ck * 2 + (kk >> 2)) * A_CHUNK_BYTES;
            const uint32_t sBh = sB + (kk >> 2) * 32768;
            uint32_t Af[4][4], Bf[8][2];
#pragma unroll
            for (int jj = 0; jj < 4; jj++) {
                uint32_t f[4];
                ldmB4(sBh, wn * 64 + jj * 16, kb, lane, f);
                Bf[2 * jj][0] = f[0]; Bf[2 * jj][1] = f[1];
                Bf[2 * jj + 1][0] = f[2]; Bf[2 * jj + 1][1] = f[3];
            }
#pragma unroll
            for (int i = 0; i < 4; i++)
                ldmA(sA, wm * 64 + i * 16, kb, lane, Af[i]);
#pragma unroll
            for (int i = 0; i < 4; i++)
#pragma unroll
                for (int j = 0; j < 8; j++)
                    mma_f16(acc[i][j], Af[i], Bf[j]);
        }

        if (ck == NCHUNK_K - 1) {
            const int tl = c / NCHUNK_K;
            const int j0 = (jt0 + tl) * BN;
            const float* yn = ynbuf + (tl & 1) * 256;
#pragma unroll
            for (int i = 0; i < 4; i++)
#pragma unroll
                for (int j = 0; j < 8; j++) {
                    int cl = wn * 64 + j * 8 + tig * 2;
                    float yn0 = yn[cl], yn1 = yn[cl + 1];
                    int col = j0 + cl;
                    fold_min(bestA[i], xnA[i], yn0, acc[i][j][0], col);
                    fold_min(bestA[i], xnA[i], yn1, acc[i][j][1], col + 1);
                    fold_min(bestB[i], xnB[i], yn0, acc[i][j][2], col);
                    fold_min(bestB[i], xnB[i], yn1, acc[i][j][3], col + 1);
                    acc[i][j][0] = acc[i][j][1] = acc[i][j][2] = acc[i][j][3] = 0.f;
                }
        }
    }

    // reduce across tig lanes (same row)
#pragma unroll
    for (int i = 0; i < 4; i++) {
#pragma unroll
        for (int off = 1; off <= 2; off <<= 1) {
            bestA[i] = umin64(bestA[i], __shfl_xor_sync(0xFFFFFFFFu, bestA[i], off));
            bestB[i] = umin64(bestB[i], __shfl_xor_sync(0xFFFFFFFFu, bestB[i], off));
        }
    }

    __syncthreads();   // ynorm slots dead; reuse region as reduce buffer
    if (t < BM) red[t] = 0xFFFFFFFFFFFFFFFFull;
    __syncthreads();
    if (tig == 0) {
#pragma unroll
        for (int i = 0; i < 4; i++) {
            atomicMin(&red[wm * 64 + i * 16 + gid], bestA[i]);
            atomicMin(&red[wm * 64 + i * 16 + gid + 8], bestB[i]);
        }
    }
    __syncthreads();
    if (t < BM) atomicMin(&g_packed[row0 + t], red[t]);
}

// ---------------- tail: batch argmax + patch map write (fused) ----------------
__global__ void batch_map_kernel(float* __restrict__ out) {
    int b = blockIdx.x, t = threadIdx.x;
    __shared__ float sv[256];
    __shared__ int   si[256];
    float bv = -1.f; int bi = PATCHES;
    for (int p = t; p < PATCHES; p += 256) {
        unsigned long long pk = g_packed[b * PATCHES + p];
        float d = __uint_as_float((unsigned)(pk >> 32));
        out[b * PATCHES + p] = sqrtf(d);
        if (d > bv || (d == bv && p < bi)) { bv = d; bi = p; }
    }
    sv[t] = bv; si[t] = bi;
    __syncthreads();
    for (int s = 128; s; s >>= 1) {
        if (t < s) {
            if (sv[t + s] > sv[t] || (sv[t + s] == sv[t] && si[t + s] < si[t])) {
                sv[t] = sv[t + s]; si[t] = si[t + s];
            }
        }
        __syncthreads();
    }
    if (t == 0) {
        int row = b * PATCHES + si[0];
        unsigned long long pk = g_packed[row];
        g_maxrow[b] = row;
        g_score[b]  = sqrtf(__uint_as_float((unsigned)(pk >> 32)));
        g_nnidx[b]  = (int)(pk & 0xFFFFFFFFull);
    }
}

// ---------------- d2: fp16 bank reads (24MB DRAM), 8 m-rows per block ----------
__global__ void d2_block_kernel() {
    __shared__ float4 nn4[B_SZ][DIM / 4];   // nn rows as fp32 (converted once)
    __shared__ float  nyn[B_SZ];
    int t = threadIdx.x, wid = t >> 5, lane = t & 31;
    for (int i = t; i < B_SZ * (DIM / 4); i += 256) {
        int b = i / (DIM / 4), v = i % (DIM / 4);
        const __half2* src = reinterpret_cast<const __half2*>(
            g_Bh + (size_t)g_nnidx[b] * DIM + v * 4);
        float2 lo = __half22float2(src[0]);
        float2 hi = __half22float2(src[1]);
        nn4[b][v] = make_float4(lo.x, lo.y, hi.x, hi.y);
    }
    if (t < B_SZ) nyn[t] = g_ynorm[g_nnidx[t]];
    __syncthreads();

    int m = blockIdx.x * 8 + wid;
    const uint2* pm2 = reinterpret_cast<const uint2*>(g_Bh + (size_t)m * DIM);
    float s[B_SZ];
#pragma unroll
    for (int b = 0; b < B_SZ; b++) s[b] = 0.f;
#pragma unroll
    for (int v = 0; v < 3; v++) {
        uint2 raw = pm2[lane + v * 32];   // 4 halves at k = (lane+v*32)*4
        float2 flo = __half22float2(*reinterpret_cast<__half2*>(&raw.x));
        float2 fhi = __half22float2(*reinterpret_cast<__half2*>(&raw.y));
#pragma unroll
        for (int b = 0; b < B_SZ; b++) {
            float4 g = nn4[b][lane + v * 32];
            s[b] += flo.x * g.x + flo.y * g.y + fhi.x * g.z + fhi.y * g.w;
        }
    }
#pragma unroll
    for (int b = 0; b < B_SZ; b++) s[b] = warp_sum(s[b]);
    if (lane == 0) {
        float ym = g_ynorm[m];
#pragma unroll
        for (int b = 0; b < B_SZ; b++)
            g_d2[b * M_BANK + m] = fmaxf(nyn[b] + ym - 2.f * s[b], 0.f);
    }
}

// ---------------- top-9 stage A: shfl-reduce rounds ----------
__global__ void topkA_kernel() {
    __shared__ unsigned long long vals[SEG_LEN];
    __shared__ unsigned long long wred[8];
    int b = blockIdx.y, seg = blockIdx.x, t = threadIdx.x;
    int wid = t >> 5, lane = t & 31;
    for (int i = t; i < SEG_LEN; i += 256) {
        int m = seg * SEG_LEN + i;
        vals[i] = ((unsigned long long)__float_as_uint(g_d2[b * M_BANK + m]) << 32)
                  | (unsigned)m;
    }
    __syncthreads();
    for (int r = 0; r < KNN; r++) {
        unsigned long long mv = umin64(umin64(vals[t], vals[t + 256]),
                                       umin64(vals[t + 512], vals[t + 768]));
#pragma unroll
        for (int off = 16; off; off >>= 1)
            mv = umin64(mv, __shfl_xor_sync(0xFFFFFFFFu, mv, off));
        if (!lane) wred[wid] = mv;
        __syncthreads();
        if (t == 0) {
            unsigned long long m = wred[0];
#pragma unroll
            for (int i = 1; i < 8; i++) m = umin64(m, wred[i]);
            g_part[(b * SEGS + seg) * KNN + r] = m;
            vals[(unsigned)m - seg * SEG_LEN] = 0xFFFFFFFFFFFFFFFFull;
        }
        __syncthreads();
    }
}

// ---------------- top-9 merge + final score (fused) ----------------
__global__ void topk_final_kernel(const float* __restrict__ E,
                                  const float* __restrict__ MB,
                                  float* __restrict__ out) {
    __shared__ unsigned long long cand[512];
    __shared__ unsigned long long red[512];
    __shared__ int   sup[KNN];
    __shared__ float d3[KNN];
    int b = blockIdx.x, t = threadIdx.x;
    cand[t] = (t < SEGS * KNN) ? g_part[b * SEGS * KNN + t]
                               : 0xFFFFFFFFFFFFFFFFull;
    __syncthreads();
    for (int r = 0; r < KNN; r++) {
        red[t] = cand[t];
        __syncthreads();
        for (int s = 256; s; s >>= 1) {
            if (t < s) red[t] = umin64(red[t], red[t + s]);
            __syncthreads();
        }
        unsigned long long sel = red[0];
        if (t == 0) sup[r] = (int)(sel & 0xFFFFFFFFull);
        if (cand[t] == sel) cand[t] = 0xFFFFFFFFFFFFFFFFull;
        __syncthreads();
    }

    int wid = t >> 5, lane = t & 31;
    int row = g_maxrow[b];
    if (wid < KNN) {
        const float* xf = E + (size_t)row * DIM;
        int sp = sup[wid];
        const float* pv = MB + (size_t)sp * DIM;
        float s = 0.f;
        for (int k = lane; k < DIM; k += 32) s += xf[k] * pv[k];
        s = warp_sum(s);
        if (!lane)
            d3[wid] = sqrtf(fmaxf(g_xnorm[row] + g_ynorm[sp] - 2.f * s, 0.f));
    }
    __syncthreads();
    if (t == 0) {
        float mx = -FLT_MAX;
        for (int j = 0; j < KNN; j++) mx = fmaxf(mx, d3[j]);
        float den = 0.f, e0 = 0.f;
        for (int j = 0; j < KNN; j++) {
            float e = expf(d3[j] - mx);
            den += e;
            if (j == 0) e0 = e;
        }
        out[N_ROWS + b] = (1.f - e0 / den) * g_score[b];
    }
}

// ---------------- launch ----------------
extern "C" void kernel_launch(void* const* d_in, const int* in_sizes, int n_in,
                              void* d_out, int out_size) {
    (void)n_in; (void)in_sizes; (void)out_size;
    const float* E  = (const float*)d_in[0];
    const float* MB = (const float*)d_in[1];
    float* out = (float*)d_out;

    cudaFuncSetAttribute(gemm_mma_kernel,
                         cudaFuncAttributeMaxDynamicSharedMemorySize, SMEM_BYTES);

    int warps = N_ROWS + M_BANK;
    prep_all_kernel<<<(warps * 32 + 255) / 256, 256>>>(E, MB);

    gemm_mma_kernel<<<dim3(ROW_TILES, GRID_Y), NTHR, SMEM_BYTES>>>();

    batch_map_kernel<<<B_SZ, 256>>>(out);
    d2_block_kernel<<<M_BANK / 8, 256>>>();
    topkA_kernel<<<dim3(SEGS, B_SZ), 256>>>();
    topk_final_kernel<<<B_SZ, 512>>>(E, MB, out);
}